// round 13
// baseline (speedup 1.0000x reference)
#include <cuda_runtime.h>
#include <cstdint>

#define HH 512
#define WW 512
#define BB 8
#define NPIX (HH*WW)
#define ITERS 50
#define CC 256.5f

// Double-buffered state + triple-buffered moment sums (zero/accum/read rotate).
__device__ float  g_u[2][BB*NPIX];
__device__ float  g_q[2][BB*NPIX];
__device__ double g_sums[3][BB][8];

__global__ void zero_sums_kernel() {
    int i = threadIdx.x;
    if (i < 3*BB*8) reinterpret_cast<double*>(g_sums)[i] = 0.0;
}

__device__ __forceinline__ float sigmoid_fast(float x) {
    float t;
    asm("tanh.approx.f32 %0, %1;" : "=f"(t) : "f"(0.5f * x));
    return fmaf(0.5f, t, 0.5f);
}

__device__ __forceinline__ uint32_t smem_u32(const void* p) {
    return (uint32_t)__cvta_generic_to_shared(p);
}

// Wait for mbarrier phase 0 completion (acquire: orders bulk-copy smem writes
// before our generic-proxy reads).
__device__ __forceinline__ void mbar_wait0(uint32_t mbar) {
    asm volatile(
        "{\n\t"
        ".reg .pred P;\n\t"
        "WAIT_%=: \n\t"
        "mbarrier.try_wait.parity.acquire.cta.shared::cta.b64 P, [%0], 0, 0x989680;\n\t"
        "@!P bra WAIT_%=;\n\t"
        "}"
        :: "r"(mbar) : "memory");
}

// Two-stage moment reduction. tid = row*8 + colgroup, so the 8 lanes of a row
// share xc: reduce (s0,sy,syy) over them (9 SHFL), park row triples in smem,
// warp 0 folds in xc and finishes.
__device__ __forceinline__ void moments3_reduce(float s0, float sy, float syy,
                                                int i0, double* dst,
                                                float (*rowred)[3], int tid) {
#pragma unroll
    for (int off = 1; off <= 4; off <<= 1) {
        s0  += __shfl_xor_sync(0xffffffffu, s0,  off);
        sy  += __shfl_xor_sync(0xffffffffu, sy,  off);
        syy += __shfl_xor_sync(0xffffffffu, syy, off);
    }
    if ((tid & 7) == 0) {
        int r = tid >> 3;
        rowred[r][0] = s0; rowred[r][1] = sy; rowred[r][2] = syy;
    }
    __syncthreads();
    if (tid < 32) {
        float a0 = rowred[tid][0], a1 = rowred[tid][1], a2 = rowred[tid][2];
        float xc = (float)(i0 + tid + 1) - CC;
        float m[6] = { a0, xc*a0, a1, xc*xc*a0, a2, xc*a1 };
#pragma unroll
        for (int off = 16; off; off >>= 1)
#pragma unroll
            for (int k = 0; k < 6; k++) m[k] += __shfl_xor_sync(0xffffffffu, m[k], off);
        if (tid == 0)
#pragma unroll
            for (int k = 0; k < 6; k++) atomicAdd(&dst[k], (double)m[k]);
    }
}

// u0 = sigmoid(o), q0 = 0, moments(u0) -> g_sums[0]. 4 px / thread, float4 I/O.
__global__ __launch_bounds__(256) void init_kernel(const float* __restrict__ o) {
    int tid = threadIdx.x;
    int b  = blockIdx.z;
    int i0 = blockIdx.y * 32, j0 = blockIdx.x * 32;
    int i = tid >> 3, j = (tid & 7) * 4;
    int gi = i0 + i, gj = j0 + j;
    int gidx = gi*WW + gj;
    const float* ob = o + (size_t)b * NPIX;

    float4 ov = *(const float4*)(ob + gidx);
    float un[4];
    un[0] = sigmoid_fast(ov.x);
    un[1] = sigmoid_fast(ov.y);
    un[2] = sigmoid_fast(ov.z);
    un[3] = sigmoid_fast(ov.w);
    *(float4*)(g_u[0] + (size_t)b*NPIX + gidx) = make_float4(un[0],un[1],un[2],un[3]);
    *(float4*)(g_q[0] + (size_t)b*NPIX + gidx) = make_float4(0.f,0.f,0.f,0.f);

    float s0 = 0.f, sy = 0.f, syy = 0.f;
#pragma unroll
    for (int k = 0; k < 4; k++) {
        float yc = (float)(gj+k+1) - CC;
        s0 += un[k]; sy += un[k]*yc; syy += un[k]*yc*yc;
    }
    __shared__ float rowred[32][3];
    moments3_reduce(s0, sy, syy, i0, g_sums[0][b], rowred, tid);
}

// One full iteration. INTERIOR=true: tile touches no image border -> bounds
// checks compile out AND the tile fill uses cp.async.bulk row copies.
template<bool INTERIOR>
__device__ __forceinline__ void step_impl(
    const float* __restrict__ ob, const float* __restrict__ u_in,
    const float* __restrict__ q_in, float* __restrict__ u_out,
    float* __restrict__ q_out, float* __restrict__ out,
    int b, int i0, int j0, int tid, int t,
    float (*u_s)[40], float (*q_s)[40], float (*t_s)[36],
    float (*txq_s)[36], float (*tyq_s)[36], float* sc, float (*rowred)[3],
    uint64_t* mbar_p)
{
    // Output strip coords (also used to prefetch o before the first sync).
    int di = tid >> 3, dj = (tid & 7) * 4;
    int dgi = i0 + di, dgj0 = j0 + dj;
    int dgidx = dgi*WW + dgj0;
    float4 ov = *(const float4*)(ob + dgidx);   // prefetch: independent of smem

    // Zero the sums buffer used two iterations from now.
    if (blockIdx.x == 0 && blockIdx.y == 0 && b == 0 && tid < BB*8)
        reinterpret_cast<double*>(g_sums[(t+2)%3])[tid] = 0.0;

    if (tid == 0) {  // scalars from fp64 moments (centered at CC)
        const double* S = g_sums[t % 3][b];
        double inv = 1.0 / S[0];
        double dx = S[1]*inv, dy = S[2]*inv;
        sc[0] = (float)dx; sc[1] = (float)dy;
        sc[2] = (float)(S[5]*inv - dx*dy);   // cossin
        sc[3] = (float)(S[3]*inv - dx*dx);   // bsin
        sc[4] = (float)(S[4]*inv - dy*dy);   // asin
    }

    // ---- Phase A: tile fill. Interior: bulk-copy rows (160B each) + mbarrier.
    //      Border: per-lane LDG with zero padding.
    if (INTERIOR) {
        uint32_t mbar = smem_u32(mbar_p);
        if (tid == 0) {
            asm volatile("mbarrier.init.shared.b64 [%0], %1;"
                         :: "r"(mbar), "r"(1) : "memory");
            // expect 70 rows x 160B = 11200 bytes (arrive count 1 consumed here)
            asm volatile("mbarrier.arrive.expect_tx.shared.b64 _, [%0], %1;"
                         :: "r"(mbar), "r"(11200) : "memory");
        }
        __syncthreads();   // mbar init + sc visible to all
        if (tid < 70) {
            bool isq = tid >= 36;
            int r = isq ? tid - 36 : tid;
            const float* src = isq ? (q_in + (i0 + r - 1)*WW + j0 - 4)
                                   : (u_in + (i0 + r - 2)*WW + j0 - 4);
            uint32_t dst = isq ? smem_u32(&q_s[r][0]) : smem_u32(&u_s[r][0]);
            asm volatile(
                "cp.async.bulk.shared::cluster.global.mbarrier::complete_tx::bytes "
                "[%0], [%1], %2, [%3];"
                :: "r"(dst), "l"(src), "r"(160), "r"(mbar) : "memory");
        }
        mbar_wait0(mbar);
    } else {
#pragma unroll
        for (int s = 0; s < 3; s++) {
            int idx = tid + 256*s;
            if (idx < 700) {
                bool isq = idx >= 360;
                int k = isq ? idx - 360 : idx;
                int r = k / 10, c = k - r*10;
                int gi = i0 + r - (isq ? 1 : 2);
                int gj = j0 + 4*c - 4;
                float4 v = make_float4(0.f,0.f,0.f,0.f);
                if ((unsigned)gi < HH && (unsigned)gj < WW)
                    v = *(const float4*)((isq ? q_in : u_in) + gi*WW + gj);
                if (isq) *(float4*)&q_s[r][4*c] = v;
                else     *(float4*)&u_s[r][4*c] = v;
            }
        }
        __syncthreads();
    }

    float dofx = sc[0], dofy = sc[1], cossin = sc[2], bsin = sc[3], asin_ = sc[4];

    // Normalized separable gaussian weights g(a)=exp(-a^2/50)/S.
    float e1 = __expf(-0.02f), e2 = __expf(-0.08f);
    float invs = 1.f / (1.f + 2.f*(e1 + e2));
    float w0 = e2*invs, w1 = e1*invs, w2 = invs;

    // ---- Phase B: gaussian column pass, 36 rows x 8 vec4 groups ----
#pragma unroll
    for (int s = 0; s < 2; s++) {
        int idx = tid + 256*s;
        if (idx < 288) {
            int r = idx >> 3, x = idx & 7;
            int g0 = 4*x;
            float4 a = *(float4*)&u_s[r][g0];
            float4 bb = *(float4*)&u_s[r][g0+4];
            float4 cc = *(float4*)&u_s[r][g0+8];
            float e[12] = {a.x,a.y,a.z,a.w, bb.x,bb.y,bb.z,bb.w, cc.x,cc.y,cc.z,cc.w};
            float4 ot;
            ot.x = w0*(e[2]+e[6]) + w1*(e[3]+e[5]) + w2*e[4];
            ot.y = w0*(e[3]+e[7]) + w1*(e[4]+e[6]) + w2*e[5];
            ot.z = w0*(e[4]+e[8]) + w1*(e[5]+e[7]) + w2*e[6];
            ot.w = w0*(e[5]+e[9]) + w1*(e[6]+e[8]) + w2*e[7];
            *(float4*)&t_s[r][g0] = ot;
        }
    }

    // ---- Phase C: q_new / Tx*q / Ty*q over halo-1 region (33 rows x 9 vec4).
    // q_new for in-tile pixels goes straight to q_out.
#pragma unroll
    for (int s = 0; s < 2; s++) {
        int idx = tid + 256*s;
        if (idx < 297) {
            int r = idx / 9, c = idx - r*9;
            int m0 = 4*c;
            int gi = i0 - 1 + r;
            float4 ca = *(float4*)&u_s[r+1][m0];
            float4 cb = *(float4*)&u_s[r+1][m0+4];
            float4 da = *(float4*)&u_s[r+2][m0];
            float4 db = *(float4*)&u_s[r+2][m0+4];
            float4 qa = *(float4*)&q_s[r][m0];
            float4 qb = *(float4*)&q_s[r][m0+4];
            float uc[4] = {ca.z, ca.w, cb.x, cb.y};   // u(i,j)
            float ur[4] = {ca.w, cb.x, cb.y, cb.z};   // u(i,j+1)
            float ud[4] = {da.z, da.w, db.x, db.y};   // u(i+1,j)
            float qq[4] = {qa.z, qa.w, qb.x, qb.y};
            float dxv = (float)(gi+1) - CC - dofx;
            int gj0c = j0 + m0 - 2;
            // Incremental Tx/Ty: d/dk Tx = bsin, d/dk Ty = cossin.
            float dyv0 = (float)(gj0c+1) - CC - dofy;
            float Txk = dyv0*bsin   - dxv*cossin;
            float Tyk = dyv0*cossin - dxv*asin_;
            float rtx[4], rty[4], rqn[4];
#pragma unroll
            for (int k = 0; k < 4; k++) {
                float inv = rsqrtf(fmaf(Txk, Txk, Tyk*Tyk) + 1e-20f);
                float nx = Txk*inv, ny = Tyk*inv;
                float qn = qq[k] - ((ud[k]-uc[k])*nx + (ur[k]-uc[k])*ny);  // TAU=1
                if (!INTERIOR) {
                    bool ok = (gi >= 0) && ((unsigned)(gj0c + k) < WW);
                    qn = ok ? qn : 0.f;
                }
                rqn[k] = qn; rtx[k] = nx*qn; rty[k] = ny*qn;
                Txk += bsin; Tyk += cossin;
            }
            *(float4*)&txq_s[r][m0] = make_float4(rtx[0],rtx[1],rtx[2],rtx[3]);
            *(float4*)&tyq_s[r][m0] = make_float4(rty[0],rty[1],rty[2],rty[3]);
            if (r >= 1) {
#pragma unroll
                for (int k = 0; k < 4; k++) {
                    int lj = m0 + k - 2;
                    if ((unsigned)lj < 32u) q_out[gi*WW + j0 + lj] = rqn[k];
                }
            }
        }
    }
    __syncthreads();

    // ---- Phase D: output, 1 vec4 strip per thread ----
    int i = di, j = dj;
    float4 t0 = *(float4*)&t_s[i  ][j];
    float4 t1 = *(float4*)&t_s[i+1][j];
    float4 t2 = *(float4*)&t_s[i+2][j];
    float4 t3 = *(float4*)&t_s[i+3][j];
    float4 t4 = *(float4*)&t_s[i+4][j];
    float ta[4] = {t0.x,t0.y,t0.z,t0.w};
    float tb[4] = {t1.x,t1.y,t1.z,t1.w};
    float tc[4] = {t2.x,t2.y,t2.z,t2.w};
    float td[4] = {t3.x,t3.y,t3.z,t3.w};
    float te[4] = {t4.x,t4.y,t4.z,t4.w};

    float4 A0 = *(float4*)&txq_s[i+1][j], A1 = *(float4*)&txq_s[i+1][j+4];
    float4 B0 = *(float4*)&txq_s[i  ][j], B1 = *(float4*)&txq_s[i  ][j+4];
    float4 Y0 = *(float4*)&tyq_s[i+1][j], Y1 = *(float4*)&tyq_s[i+1][j+4];
    float ax[8] = {A0.x,A0.y,A0.z,A0.w, A1.x,A1.y,A1.z,A1.w};
    float bx[8] = {B0.x,B0.y,B0.z,B0.w, B1.x,B1.y,B1.z,B1.w};
    float yx[8] = {Y0.x,Y0.y,Y0.z,Y0.w, Y1.x,Y1.y,Y1.z,Y1.w};

    float oo[4] = {ov.x, ov.y, ov.z, ov.w};

    // row border mass for p = conv(1-2u)
    float ra = 1.f;
    if (!INTERIOR) {
        if (dgi == 0) ra -= w0 + w1; else if (dgi == 1) ra -= w0;
        if (dgi == HH-1) ra -= w0 + w1; else if (dgi == HH-2) ra -= w0;
    }

    float s0 = 0.f, sy = 0.f, syy = 0.f;
    float uo[4], ao[4];
    bool wout = (out != nullptr);
#pragma unroll
    for (int k = 0; k < 4; k++) {
        float Tq = ax[k+2] - bx[k+2] + yx[k+2] - yx[k+1];
        float conv = w0*(ta[k]+te[k]) + w1*(tb[k]+td[k]) + w2*tc[k];
        float p;
        if (INTERIOR) {
            p = 1.f - 2.f*conv;
        } else {
            int gj = dgj0 + k;
            float rb = 1.f;
            if (gj == 0) rb -= w0 + w1; else if (gj == 1) rb -= w0;
            if (gj == WW-1) rb -= w0 + w1; else if (gj == WW-2) rb -= w0;
            p = ra*rb - 2.f*conv;
        }
        float arg = oo[k] - p - Tq;          // LAM = EPS = 1
        float un  = sigmoid_fast(arg);
        uo[k] = un; ao[k] = arg;
        float yc = (float)(dgj0+k+1) - CC;
        s0 += un; sy += un*yc; syy += un*yc*yc;
    }
    *(float4*)(u_out + dgidx) = make_float4(uo[0],uo[1],uo[2],uo[3]);
    if (wout)
        *(float4*)(out + (size_t)b*NPIX + dgidx) = make_float4(ao[0],ao[1],ao[2],ao[3]);

    moments3_reduce(s0, sy, syy, i0, g_sums[(t+1)%3][b], rowred, tid);
}

__global__ __launch_bounds__(256, 5) void step_kernel(const float* __restrict__ o,
                                                      float* __restrict__ out, int t)
{
    __shared__ float u_s[36][40];
    __shared__ float q_s[34][40];
    __shared__ float t_s[36][36];
    __shared__ float txq_s[33][36];
    __shared__ float tyq_s[33][36];
    __shared__ float sc[5];
    __shared__ float rowred[32][3];
    __shared__ __align__(8) uint64_t mbar_s;

    int tid = threadIdx.x;
    int b  = blockIdx.z;
    int i0 = blockIdx.y * 32, j0 = blockIdx.x * 32;

    const float* u_in  = g_u[t & 1]     + (size_t)b * NPIX;
    const float* q_in  = g_q[t & 1]     + (size_t)b * NPIX;
    float*       u_out = g_u[(t+1) & 1] + (size_t)b * NPIX;
    float*       q_out = g_q[(t+1) & 1] + (size_t)b * NPIX;
    const float* ob    = o              + (size_t)b * NPIX;

    // Block-uniform branch: tile needs no border handling anywhere.
    bool interior = (blockIdx.x > 0) & (blockIdx.x < 15) &
                    (blockIdx.y > 0) & (blockIdx.y < 15);
    if (interior)
        step_impl<true >(ob, u_in, q_in, u_out, q_out, out, b, i0, j0, tid, t,
                         u_s, q_s, t_s, txq_s, tyq_s, sc, rowred, &mbar_s);
    else
        step_impl<false>(ob, u_in, q_in, u_out, q_out, out, b, i0, j0, tid, t,
                         u_s, q_s, t_s, txq_s, tyq_s, sc, rowred, &mbar_s);
}

extern "C" void kernel_launch(void* const* d_in, const int* in_sizes, int n_in,
                              void* d_out, int out_size) {
    const float* o = (const float*)d_in[0];
    float* out = (float*)d_out;
    (void)in_sizes; (void)n_in; (void)out_size;

    dim3 grid(WW/32, HH/32, BB);

    zero_sums_kernel<<<1, 256>>>();
    init_kernel<<<grid, 256>>>(o);
    for (int t = 0; t < ITERS; t++)
        step_kernel<<<grid, 256>>>(o, (t == ITERS-1) ? out : nullptr, t);
}

// round 14
// speedup vs baseline: 1.6098x; 1.6098x over previous
#include <cuda_runtime.h>
#include <cstdint>

#define HH 512
#define WW 512
#define BB 8
#define NPIX (HH*WW)
#define ITERS 50
#define CC 256.5f

// Normalized separable gaussian weights g(a)=exp(-a^2/50)/S, computed in fp64.
#define W0 0.19205060f
#define W1 0.20392635f
#define W2 0.20804594f

// Double-buffered state + triple-buffered moment sums (zero/accum/read rotate).
__device__ float  g_u[2][BB*NPIX];
__device__ float  g_q[2][BB*NPIX];
__device__ double g_sums[3][BB][8];

__global__ void zero_sums_kernel() {
    int i = threadIdx.x;
    if (i < 3*BB*8) reinterpret_cast<double*>(g_sums)[i] = 0.0;
}

__device__ __forceinline__ float sigmoid_fast(float x) {
    float t;
    asm("tanh.approx.f32 %0, %1;" : "=f"(t) : "f"(0.5f * x));
    return fmaf(0.5f, t, 0.5f);
}

// Two-stage moment reduction. tid = row*8 + colgroup, so the 8 lanes of a row
// share xc: reduce (s0,sy,syy) over them (9 SHFL), park row triples in smem,
// warp 0 folds in xc and finishes.
__device__ __forceinline__ void moments3_reduce(float s0, float sy, float syy,
                                                int i0, double* dst,
                                                float (*rowred)[3], int tid) {
#pragma unroll
    for (int off = 1; off <= 4; off <<= 1) {
        s0  += __shfl_xor_sync(0xffffffffu, s0,  off);
        sy  += __shfl_xor_sync(0xffffffffu, sy,  off);
        syy += __shfl_xor_sync(0xffffffffu, syy, off);
    }
    if ((tid & 7) == 0) {
        int r = tid >> 3;
        rowred[r][0] = s0; rowred[r][1] = sy; rowred[r][2] = syy;
    }
    __syncthreads();
    if (tid < 32) {
        float a0 = rowred[tid][0], a1 = rowred[tid][1], a2 = rowred[tid][2];
        float xc = (float)(i0 + tid + 1) - CC;
        float m[6] = { a0, xc*a0, a1, xc*xc*a0, a2, xc*a1 };
#pragma unroll
        for (int off = 16; off; off >>= 1)
#pragma unroll
            for (int k = 0; k < 6; k++) m[k] += __shfl_xor_sync(0xffffffffu, m[k], off);
        if (tid == 0)
#pragma unroll
            for (int k = 0; k < 6; k++) atomicAdd(&dst[k], (double)m[k]);
    }
}

// u0 = sigmoid(o), q0 = 0, moments(u0) -> g_sums[0]. 4 px / thread, float4 I/O.
__global__ __launch_bounds__(256) void init_kernel(const float* __restrict__ o) {
    int tid = threadIdx.x;
    int b  = blockIdx.z;
    int i0 = blockIdx.y * 32, j0 = blockIdx.x * 32;
    int i = tid >> 3, j = (tid & 7) * 4;
    int gi = i0 + i, gj = j0 + j;
    int gidx = gi*WW + gj;
    const float* ob = o + (size_t)b * NPIX;

    float4 ov = *(const float4*)(ob + gidx);
    float un[4];
    un[0] = sigmoid_fast(ov.x);
    un[1] = sigmoid_fast(ov.y);
    un[2] = sigmoid_fast(ov.z);
    un[3] = sigmoid_fast(ov.w);
    *(float4*)(g_u[0] + (size_t)b*NPIX + gidx) = make_float4(un[0],un[1],un[2],un[3]);
    *(float4*)(g_q[0] + (size_t)b*NPIX + gidx) = make_float4(0.f,0.f,0.f,0.f);

    float s0 = 0.f, sy = 0.f, syy = 0.f;
#pragma unroll
    for (int k = 0; k < 4; k++) {
        float yc = (float)(gj+k+1) - CC;
        s0 += un[k]; sy += un[k]*yc; syy += un[k]*yc*yc;
    }
    __shared__ float rowred[32][3];
    moments3_reduce(s0, sy, syy, i0, g_sums[0][b], rowred, tid);
}

// One full iteration. INTERIOR=true: tile touches no image border -> all
// bounds checks and border-mass corrections compile out.
template<bool INTERIOR>
__device__ __forceinline__ void step_impl(
    const float* __restrict__ ob, const float* __restrict__ u_in,
    const float* __restrict__ q_in, float* __restrict__ u_out,
    float* __restrict__ q_out, float* __restrict__ out,
    int b, int i0, int j0, int tid, int t,
    float (*u_s)[40], float (*q_s)[40], float (*t_s)[36],
    float (*txq_s)[36], float (*tyq_s)[36], float* sc, float (*rowred)[3])
{
    // Output strip coords (also used to prefetch o before the first sync).
    int di = tid >> 3, dj = (tid & 7) * 4;
    int dgi = i0 + di, dgj0 = j0 + dj;
    int dgidx = dgi*WW + dgj0;
    float4 ov = *(const float4*)(ob + dgidx);   // prefetch: independent of smem

    // Zero the sums buffer used two iterations from now.
    if (blockIdx.x == 0 && blockIdx.y == 0 && b == 0 && tid < BB*8)
        reinterpret_cast<double*>(g_sums[(t+2)%3])[tid] = 0.0;

    if (tid == 0) {  // scalars from fp64 moments (centered at CC)
        const double* S = g_sums[t % 3][b];
        double inv = 1.0 / S[0];
        double dx = S[1]*inv, dy = S[2]*inv;
        sc[0] = (float)dx; sc[1] = (float)dy;
        sc[2] = (float)(S[5]*inv - dx*dy);   // cossin
        sc[3] = (float)(S[3]*inv - dx*dx);   // bsin
        sc[4] = (float)(S[4]*inv - dy*dy);   // asin
    }

    // ---- Phase A: vectorized tile loads (u: 36x10 vec4, q: 34x10 vec4) ----
#pragma unroll
    for (int s = 0; s < 3; s++) {
        int idx = tid + 256*s;
        if (idx < 700) {
            bool isq = idx >= 360;
            int k = isq ? idx - 360 : idx;
            int r = k / 10, c = k - r*10;
            int gi = i0 + r - (isq ? 1 : 2);
            int gj = j0 + 4*c - 4;
            if (INTERIOR) {
                float4 v = *(const float4*)((isq ? q_in : u_in) + gi*WW + gj);
                if (isq) *(float4*)&q_s[r][4*c] = v;
                else     *(float4*)&u_s[r][4*c] = v;
            } else {
                float4 v = make_float4(0.f,0.f,0.f,0.f);
                if ((unsigned)gi < HH && (unsigned)gj < WW)
                    v = *(const float4*)((isq ? q_in : u_in) + gi*WW + gj);
                if (isq) *(float4*)&q_s[r][4*c] = v;
                else     *(float4*)&u_s[r][4*c] = v;
            }
        }
    }
    __syncthreads();

    float dofx = sc[0], dofy = sc[1], cossin = sc[2], bsin = sc[3], asin_ = sc[4];

    // ---- Phase B: gaussian column pass, 36 rows x 8 vec4 groups ----
#pragma unroll
    for (int s = 0; s < 2; s++) {
        int idx = tid + 256*s;
        if (idx < 288) {
            int r = idx >> 3, x = idx & 7;
            int g0 = 4*x;
            float4 a = *(float4*)&u_s[r][g0];
            float4 bb = *(float4*)&u_s[r][g0+4];
            float4 cc = *(float4*)&u_s[r][g0+8];
            float e[12] = {a.x,a.y,a.z,a.w, bb.x,bb.y,bb.z,bb.w, cc.x,cc.y,cc.z,cc.w};
            float4 ot;
            ot.x = W0*(e[2]+e[6]) + W1*(e[3]+e[5]) + W2*e[4];
            ot.y = W0*(e[3]+e[7]) + W1*(e[4]+e[6]) + W2*e[5];
            ot.z = W0*(e[4]+e[8]) + W1*(e[5]+e[7]) + W2*e[6];
            ot.w = W0*(e[5]+e[9]) + W1*(e[6]+e[8]) + W2*e[7];
            *(float4*)&t_s[r][g0] = ot;
        }
    }

    // ---- Phase C: q_new / Tx*q / Ty*q over halo-1 region (33 rows x 9 vec4).
    // q_new for in-tile pixels goes straight to q_out as aligned float2 pairs.
#pragma unroll
    for (int s = 0; s < 2; s++) {
        int idx = tid + 256*s;
        if (idx < 297) {
            int r = idx / 9, c = idx - r*9;
            int m0 = 4*c;
            int gi = i0 - 1 + r;
            float4 ca = *(float4*)&u_s[r+1][m0];
            float4 cb = *(float4*)&u_s[r+1][m0+4];
            float4 da = *(float4*)&u_s[r+2][m0];
            float4 db = *(float4*)&u_s[r+2][m0+4];
            float4 qa = *(float4*)&q_s[r][m0];
            float4 qb = *(float4*)&q_s[r][m0+4];
            float uc[4] = {ca.z, ca.w, cb.x, cb.y};   // u(i,j)
            float ur[4] = {ca.w, cb.x, cb.y, cb.z};   // u(i,j+1)
            float ud[4] = {da.z, da.w, db.x, db.y};   // u(i+1,j)
            float qq[4] = {qa.z, qa.w, qb.x, qb.y};
            float dxv = (float)(gi+1) - CC - dofx;
            int gj0c = j0 + m0 - 2;
            // Incremental Tx/Ty: d/dk Tx = bsin, d/dk Ty = cossin.
            float dyv0 = (float)(gj0c+1) - CC - dofy;
            float Txk = dyv0*bsin   - dxv*cossin;
            float Tyk = dyv0*cossin - dxv*asin_;
            float rtx[4], rty[4], rqn[4];
#pragma unroll
            for (int k = 0; k < 4; k++) {
                float inv = rsqrtf(fmaf(Txk, Txk, Tyk*Tyk) + 1e-20f);
                float nx = Txk*inv, ny = Tyk*inv;
                float qn = qq[k] - ((ud[k]-uc[k])*nx + (ur[k]-uc[k])*ny);  // TAU=1
                if (!INTERIOR) {
                    bool ok = (gi >= 0) && ((unsigned)(gj0c + k) < WW);
                    qn = ok ? qn : 0.f;
                }
                rqn[k] = qn; rtx[k] = nx*qn; rty[k] = ny*qn;
                Txk += bsin; Tyk += cossin;
            }
            *(float4*)&txq_s[r][m0] = make_float4(rtx[0],rtx[1],rtx[2],rtx[3]);
            *(float4*)&tyq_s[r][m0] = make_float4(rty[0],rty[1],rty[2],rty[3]);
            if (r >= 1) {
                // lj = m0-2+k; aligned float2 pairs, each fully in or out of [0,32).
                float* qrow = q_out + gi*WW + j0;
                if (c >= 1) *(float2*)(qrow + m0 - 2) = make_float2(rqn[0], rqn[1]);
                if (c <= 7) *(float2*)(qrow + m0    ) = make_float2(rqn[2], rqn[3]);
            }
        }
    }
    __syncthreads();

    // ---- Phase D: output, 1 vec4 strip per thread ----
    int i = di, j = dj;
    float4 t0 = *(float4*)&t_s[i  ][j];
    float4 t1 = *(float4*)&t_s[i+1][j];
    float4 t2 = *(float4*)&t_s[i+2][j];
    float4 t3 = *(float4*)&t_s[i+3][j];
    float4 t4 = *(float4*)&t_s[i+4][j];
    float ta[4] = {t0.x,t0.y,t0.z,t0.w};
    float tb[4] = {t1.x,t1.y,t1.z,t1.w};
    float tc[4] = {t2.x,t2.y,t2.z,t2.w};
    float td[4] = {t3.x,t3.y,t3.z,t3.w};
    float te[4] = {t4.x,t4.y,t4.z,t4.w};

    float4 A0 = *(float4*)&txq_s[i+1][j], A1 = *(float4*)&txq_s[i+1][j+4];
    float4 B0 = *(float4*)&txq_s[i  ][j], B1 = *(float4*)&txq_s[i  ][j+4];
    float4 Y0 = *(float4*)&tyq_s[i+1][j], Y1 = *(float4*)&tyq_s[i+1][j+4];
    float ax[8] = {A0.x,A0.y,A0.z,A0.w, A1.x,A1.y,A1.z,A1.w};
    float bx[8] = {B0.x,B0.y,B0.z,B0.w, B1.x,B1.y,B1.z,B1.w};
    float yx[8] = {Y0.x,Y0.y,Y0.z,Y0.w, Y1.x,Y1.y,Y1.z,Y1.w};

    float oo[4] = {ov.x, ov.y, ov.z, ov.w};

    // row border mass for p = conv(1-2u)
    float ra = 1.f;
    if (!INTERIOR) {
        if (dgi == 0) ra -= W0 + W1; else if (dgi == 1) ra -= W0;
        if (dgi == HH-1) ra -= W0 + W1; else if (dgi == HH-2) ra -= W0;
    }

    float s0 = 0.f, sy = 0.f, syy = 0.f;
    float uo[4], ao[4];
    bool wout = (out != nullptr);
#pragma unroll
    for (int k = 0; k < 4; k++) {
        float Tq = ax[k+2] - bx[k+2] + yx[k+2] - yx[k+1];
        float conv = W0*(ta[k]+te[k]) + W1*(tb[k]+td[k]) + W2*tc[k];
        float p;
        if (INTERIOR) {
            p = 1.f - 2.f*conv;
        } else {
            int gj = dgj0 + k;
            float rb = 1.f;
            if (gj == 0) rb -= W0 + W1; else if (gj == 1) rb -= W0;
            if (gj == WW-1) rb -= W0 + W1; else if (gj == WW-2) rb -= W0;
            p = ra*rb - 2.f*conv;
        }
        float arg = oo[k] - p - Tq;          // LAM = EPS = 1
        float un  = sigmoid_fast(arg);
        uo[k] = un; ao[k] = arg;
        float yc = (float)(dgj0+k+1) - CC;
        s0 += un; sy += un*yc; syy += un*yc*yc;
    }
    *(float4*)(u_out + dgidx) = make_float4(uo[0],uo[1],uo[2],uo[3]);
    if (wout)
        *(float4*)(out + (size_t)b*NPIX + dgidx) = make_float4(ao[0],ao[1],ao[2],ao[3]);

    moments3_reduce(s0, sy, syy, i0, g_sums[(t+1)%3][b], rowred, tid);
}

__global__ __launch_bounds__(256, 5) void step_kernel(const float* __restrict__ o,
                                                      float* __restrict__ out, int t)
{
    __shared__ float u_s[36][40];
    __shared__ float q_s[34][40];
    __shared__ float t_s[36][36];
    __shared__ float txq_s[33][36];
    __shared__ float tyq_s[33][36];
    __shared__ float sc[5];
    __shared__ float rowred[32][3];

    int tid = threadIdx.x;
    int b  = blockIdx.z;
    int i0 = blockIdx.y * 32, j0 = blockIdx.x * 32;

    const float* u_in  = g_u[t & 1]     + (size_t)b * NPIX;
    const float* q_in  = g_q[t & 1]     + (size_t)b * NPIX;
    float*       u_out = g_u[(t+1) & 1] + (size_t)b * NPIX;
    float*       q_out = g_q[(t+1) & 1] + (size_t)b * NPIX;
    const float* ob    = o              + (size_t)b * NPIX;

    // Block-uniform branch: tile needs no border handling anywhere.
    bool interior = (blockIdx.x > 0) & (blockIdx.x < 15) &
                    (blockIdx.y > 0) & (blockIdx.y < 15);
    if (interior)
        step_impl<true >(ob, u_in, q_in, u_out, q_out, out, b, i0, j0, tid, t,
                         u_s, q_s, t_s, txq_s, tyq_s, sc, rowred);
    else
        step_impl<false>(ob, u_in, q_in, u_out, q_out, out, b, i0, j0, tid, t,
                         u_s, q_s, t_s, txq_s, tyq_s, sc, rowred);
}

extern "C" void kernel_launch(void* const* d_in, const int* in_sizes, int n_in,
                              void* d_out, int out_size) {
    const float* o = (const float*)d_in[0];
    float* out = (float*)d_out;
    (void)in_sizes; (void)n_in; (void)out_size;

    dim3 grid(WW/32, HH/32, BB);

    zero_sums_kernel<<<1, 256>>>();
    init_kernel<<<grid, 256>>>(o);
    for (int t = 0; t < ITERS; t++)
        step_kernel<<<grid, 256>>>(o, (t == ITERS-1) ? out : nullptr, t);
}

// round 15
// speedup vs baseline: 1.6853x; 1.0469x over previous
#include <cuda_runtime.h>
#include <cstdint>

#define HH 512
#define WW 512
#define BB 8
#define NPIX (HH*WW)
#define ITERS 50
#define CC 256.5f

// Double-buffered state + triple-buffered moment sums (zero/accum/read rotate).
__device__ float  g_u[2][BB*NPIX];
__device__ float  g_q[2][BB*NPIX];
__device__ double g_sums[3][BB][8];

__global__ void zero_sums_kernel() {
    int i = threadIdx.x;
    if (i < 3*BB*8) reinterpret_cast<double*>(g_sums)[i] = 0.0;
}

__device__ __forceinline__ float sigmoid_fast(float x) {
    float t;
    asm("tanh.approx.f32 %0, %1;" : "=f"(t) : "f"(0.5f * x));
    return fmaf(0.5f, t, 0.5f);
}

// Two-stage moment reduction. tid = row*8 + colgroup, so the 8 lanes of a row
// share xc: reduce (s0,sy,syy) over them (9 SHFL), park row triples in smem.
// Barrier is split: warps 1-7 arrive and exit; only warp 0 waits and finishes.
__device__ __forceinline__ void moments3_reduce(float s0, float sy, float syy,
                                                int i0, double* dst,
                                                float (*rowred)[3], int tid) {
#pragma unroll
    for (int off = 1; off <= 4; off <<= 1) {
        s0  += __shfl_xor_sync(0xffffffffu, s0,  off);
        sy  += __shfl_xor_sync(0xffffffffu, sy,  off);
        syy += __shfl_xor_sync(0xffffffffu, syy, off);
    }
    if ((tid & 7) == 0) {
        int r = tid >> 3;
        rowred[r][0] = s0; rowred[r][1] = sy; rowred[r][2] = syy;
    }
    if (tid < 32) {
        asm volatile("bar.sync 1, 256;" ::: "memory");   // wait for all arrivals
        float a0 = rowred[tid][0], a1 = rowred[tid][1], a2 = rowred[tid][2];
        float xc = (float)(i0 + tid + 1) - CC;
        float m[6] = { a0, xc*a0, a1, xc*xc*a0, a2, xc*a1 };
#pragma unroll
        for (int off = 16; off; off >>= 1)
#pragma unroll
            for (int k = 0; k < 6; k++) m[k] += __shfl_xor_sync(0xffffffffu, m[k], off);
        if (tid == 0)
#pragma unroll
            for (int k = 0; k < 6; k++) atomicAdd(&dst[k], (double)m[k]);
    } else {
        asm volatile("bar.arrive 1, 256;" ::: "memory"); // no wait; warp may exit
    }
}

// u0 = sigmoid(o), q0 = 0, moments(u0) -> g_sums[0]. 4 px / thread, float4 I/O.
__global__ __launch_bounds__(256) void init_kernel(const float* __restrict__ o) {
    int tid = threadIdx.x;
    int b  = blockIdx.z;
    int i0 = blockIdx.y * 32, j0 = blockIdx.x * 32;
    int i = tid >> 3, j = (tid & 7) * 4;
    int gi = i0 + i, gj = j0 + j;
    int gidx = gi*WW + gj;
    const float* ob = o + (size_t)b * NPIX;

    float4 ov = *(const float4*)(ob + gidx);
    float un[4];
    un[0] = sigmoid_fast(ov.x);
    un[1] = sigmoid_fast(ov.y);
    un[2] = sigmoid_fast(ov.z);
    un[3] = sigmoid_fast(ov.w);
    *(float4*)(g_u[0] + (size_t)b*NPIX + gidx) = make_float4(un[0],un[1],un[2],un[3]);
    *(float4*)(g_q[0] + (size_t)b*NPIX + gidx) = make_float4(0.f,0.f,0.f,0.f);

    float s0 = 0.f, sy = 0.f, syy = 0.f;
#pragma unroll
    for (int k = 0; k < 4; k++) {
        float yc = (float)(gj+k+1) - CC;
        s0 += un[k]; sy += un[k]*yc; syy += un[k]*yc*yc;
    }
    __shared__ float rowred[32][3];
    moments3_reduce(s0, sy, syy, i0, g_sums[0][b], rowred, tid);
}

// One full iteration. INTERIOR=true: tile touches no image border -> all
// bounds checks and border-mass corrections compile out.
template<bool INTERIOR>
__device__ __forceinline__ void step_impl(
    const float* __restrict__ ob, const float* __restrict__ u_in,
    const float* __restrict__ q_in, float* __restrict__ u_out,
    float* __restrict__ q_out, float* __restrict__ out,
    int b, int i0, int j0, int tid, int t,
    float (*u_s)[40], float (*q_s)[40], float (*t_s)[36],
    float (*txq_s)[36], float (*tyq_s)[36], float* sc, float (*rowred)[3])
{
    // Output strip coords (also used to prefetch o before the first sync).
    int di = tid >> 3, dj = (tid & 7) * 4;
    int dgi = i0 + di, dgj0 = j0 + dj;
    int dgidx = dgi*WW + dgj0;
    float4 ov = *(const float4*)(ob + dgidx);   // prefetch: independent of smem

    // Zero the sums buffer used two iterations from now.
    if (blockIdx.x == 0 && blockIdx.y == 0 && b == 0 && tid < BB*8)
        reinterpret_cast<double*>(g_sums[(t+2)%3])[tid] = 0.0;

    if (tid == 0) {  // scalars from fp64 moments (centered at CC)
        const double* S = g_sums[t % 3][b];
        double inv = 1.0 / S[0];
        double dx = S[1]*inv, dy = S[2]*inv;
        sc[0] = (float)dx; sc[1] = (float)dy;
        sc[2] = (float)(S[5]*inv - dx*dy);   // cossin
        sc[3] = (float)(S[3]*inv - dx*dx);   // bsin
        sc[4] = (float)(S[4]*inv - dy*dy);   // asin
    }

    // ---- Phase A: tile loads (u: 36x10 vec4 = 360 items, q: 34x10 = 340).
    // Interior path is straight-line with all LDGs issued before any STS (MLP=3).
    if (INTERIOR) {
        // item 0: always u (idx = tid in [0,360))
        int r0 = tid / 10, c0 = tid - r0*10;
        const float* p0 = u_in + (i0 + r0 - 2)*WW + (j0 + 4*c0 - 4);
        // item 1: u if tid<104 (idx=tid+256<360), else q (k = tid-104)
        bool l1u = tid < 104;
        int k1 = l1u ? tid + 256 : tid - 104;
        int r1 = k1 / 10, c1 = k1 - r1*10;
        const float* p1 = (l1u ? u_in + (i0 + r1 - 2)*WW
                               : q_in + (i0 + r1 - 1)*WW) + (j0 + 4*c1 - 4);
        // item 2: q (k = tid+152), valid while tid<188
        bool has2 = tid < 188;
        int k2 = tid + 152;
        int r2 = k2 / 10, c2 = k2 - r2*10;
        const float* p2 = q_in + (i0 + r2 - 1)*WW + (j0 + 4*c2 - 4);

        float4 v0 = *(const float4*)p0;
        float4 v1 = *(const float4*)p1;
        float4 v2 = make_float4(0.f,0.f,0.f,0.f);
        if (has2) v2 = *(const float4*)p2;

        *(float4*)&u_s[r0][4*c0] = v0;
        if (l1u) *(float4*)&u_s[r1][4*c1] = v1;
        else     *(float4*)&q_s[r1][4*c1] = v1;
        if (has2) *(float4*)&q_s[r2][4*c2] = v2;
    } else {
#pragma unroll
        for (int s = 0; s < 3; s++) {
            int idx = tid + 256*s;
            if (idx < 700) {
                bool isq = idx >= 360;
                int k = isq ? idx - 360 : idx;
                int r = k / 10, c = k - r*10;
                int gi = i0 + r - (isq ? 1 : 2);
                int gj = j0 + 4*c - 4;
                float4 v = make_float4(0.f,0.f,0.f,0.f);
                if ((unsigned)gi < HH && (unsigned)gj < WW)
                    v = *(const float4*)((isq ? q_in : u_in) + gi*WW + gj);
                if (isq) *(float4*)&q_s[r][4*c] = v;
                else     *(float4*)&u_s[r][4*c] = v;
            }
        }
    }
    __syncthreads();

    float dofx = sc[0], dofy = sc[1], cossin = sc[2], bsin = sc[3], asin_ = sc[4];

    // Normalized separable gaussian weights g(a)=exp(-a^2/50)/S.
    float e1 = __expf(-0.02f), e2 = __expf(-0.08f);
    float invs = 1.f / (1.f + 2.f*(e1 + e2));
    float w0 = e2*invs, w1 = e1*invs, w2 = invs;

    // ---- Phase B: gaussian column pass, 36 rows x 8 vec4 groups ----
#pragma unroll
    for (int s = 0; s < 2; s++) {
        int idx = tid + 256*s;
        if (idx < 288) {
            int r = idx >> 3, x = idx & 7;
            int g0 = 4*x;
            float4 a = *(float4*)&u_s[r][g0];
            float4 bb = *(float4*)&u_s[r][g0+4];
            float4 cc = *(float4*)&u_s[r][g0+8];
            float e[12] = {a.x,a.y,a.z,a.w, bb.x,bb.y,bb.z,bb.w, cc.x,cc.y,cc.z,cc.w};
            float4 ot;
            ot.x = w0*(e[2]+e[6]) + w1*(e[3]+e[5]) + w2*e[4];
            ot.y = w0*(e[3]+e[7]) + w1*(e[4]+e[6]) + w2*e[5];
            ot.z = w0*(e[4]+e[8]) + w1*(e[5]+e[7]) + w2*e[6];
            ot.w = w0*(e[5]+e[9]) + w1*(e[6]+e[8]) + w2*e[7];
            *(float4*)&t_s[r][g0] = ot;
        }
    }

    // ---- Phase C: q_new / Tx*q / Ty*q over halo-1 region (33 rows x 9 vec4).
    // q_new for in-tile pixels goes straight to q_out.
#pragma unroll
    for (int s = 0; s < 2; s++) {
        int idx = tid + 256*s;
        if (idx < 297) {
            int r = idx / 9, c = idx - r*9;
            int m0 = 4*c;
            int gi = i0 - 1 + r;
            float4 ca = *(float4*)&u_s[r+1][m0];
            float4 cb = *(float4*)&u_s[r+1][m0+4];
            float4 da = *(float4*)&u_s[r+2][m0];
            float4 db = *(float4*)&u_s[r+2][m0+4];
            float4 qa = *(float4*)&q_s[r][m0];
            float4 qb = *(float4*)&q_s[r][m0+4];
            float uc[4] = {ca.z, ca.w, cb.x, cb.y};   // u(i,j)
            float ur[4] = {ca.w, cb.x, cb.y, cb.z};   // u(i,j+1)
            float ud[4] = {da.z, da.w, db.x, db.y};   // u(i+1,j)
            float qq[4] = {qa.z, qa.w, qb.x, qb.y};
            float dxv = (float)(gi+1) - CC - dofx;
            int gj0c = j0 + m0 - 2;
            // Incremental Tx/Ty: d/dk Tx = bsin, d/dk Ty = cossin.
            float dyv0 = (float)(gj0c+1) - CC - dofy;
            float Txk = dyv0*bsin   - dxv*cossin;
            float Tyk = dyv0*cossin - dxv*asin_;
            float rtx[4], rty[4], rqn[4];
#pragma unroll
            for (int k = 0; k < 4; k++) {
                float inv = rsqrtf(fmaf(Txk, Txk, Tyk*Tyk) + 1e-20f);
                float nx = Txk*inv, ny = Tyk*inv;
                float qn = qq[k] - ((ud[k]-uc[k])*nx + (ur[k]-uc[k])*ny);  // TAU=1
                if (!INTERIOR) {
                    bool ok = (gi >= 0) && ((unsigned)(gj0c + k) < WW);
                    qn = ok ? qn : 0.f;
                }
                rqn[k] = qn; rtx[k] = nx*qn; rty[k] = ny*qn;
                Txk += bsin; Tyk += cossin;
            }
            *(float4*)&txq_s[r][m0] = make_float4(rtx[0],rtx[1],rtx[2],rtx[3]);
            *(float4*)&tyq_s[r][m0] = make_float4(rty[0],rty[1],rty[2],rty[3]);
            if (r >= 1) {
#pragma unroll
                for (int k = 0; k < 4; k++) {
                    int lj = m0 + k - 2;
                    if ((unsigned)lj < 32u) q_out[gi*WW + j0 + lj] = rqn[k];
                }
            }
        }
    }
    __syncthreads();

    // ---- Phase D: output, 1 vec4 strip per thread ----
    int i = di, j = dj;
    float4 t0 = *(float4*)&t_s[i  ][j];
    float4 t1 = *(float4*)&t_s[i+1][j];
    float4 t2 = *(float4*)&t_s[i+2][j];
    float4 t3 = *(float4*)&t_s[i+3][j];
    float4 t4 = *(float4*)&t_s[i+4][j];
    float ta[4] = {t0.x,t0.y,t0.z,t0.w};
    float tb[4] = {t1.x,t1.y,t1.z,t1.w};
    float tc[4] = {t2.x,t2.y,t2.z,t2.w};
    float td[4] = {t3.x,t3.y,t3.z,t3.w};
    float te[4] = {t4.x,t4.y,t4.z,t4.w};

    float4 A0 = *(float4*)&txq_s[i+1][j], A1 = *(float4*)&txq_s[i+1][j+4];
    float4 B0 = *(float4*)&txq_s[i  ][j], B1 = *(float4*)&txq_s[i  ][j+4];
    float4 Y0 = *(float4*)&tyq_s[i+1][j], Y1 = *(float4*)&tyq_s[i+1][j+4];
    float ax[8] = {A0.x,A0.y,A0.z,A0.w, A1.x,A1.y,A1.z,A1.w};
    float bx[8] = {B0.x,B0.y,B0.z,B0.w, B1.x,B1.y,B1.z,B1.w};
    float yx[8] = {Y0.x,Y0.y,Y0.z,Y0.w, Y1.x,Y1.y,Y1.z,Y1.w};

    float oo[4] = {ov.x, ov.y, ov.z, ov.w};

    // row border mass for p = conv(1-2u)
    float ra = 1.f;
    if (!INTERIOR) {
        if (dgi == 0) ra -= w0 + w1; else if (dgi == 1) ra -= w0;
        if (dgi == HH-1) ra -= w0 + w1; else if (dgi == HH-2) ra -= w0;
    }

    float s0 = 0.f, sy = 0.f, syy = 0.f;
    float uo[4], ao[4];
    bool wout = (out != nullptr);
#pragma unroll
    for (int k = 0; k < 4; k++) {
        float Tq = ax[k+2] - bx[k+2] + yx[k+2] - yx[k+1];
        float conv = w0*(ta[k]+te[k]) + w1*(tb[k]+td[k]) + w2*tc[k];
        float p;
        if (INTERIOR) {
            p = 1.f - 2.f*conv;
        } else {
            int gj = dgj0 + k;
            float rb = 1.f;
            if (gj == 0) rb -= w0 + w1; else if (gj == 1) rb -= w0;
            if (gj == WW-1) rb -= w0 + w1; else if (gj == WW-2) rb -= w0;
            p = ra*rb - 2.f*conv;
        }
        float arg = oo[k] - p - Tq;          // LAM = EPS = 1
        float un  = sigmoid_fast(arg);
        uo[k] = un; ao[k] = arg;
        float yc = (float)(dgj0+k+1) - CC;
        s0 += un; sy += un*yc; syy += un*yc*yc;
    }
    *(float4*)(u_out + dgidx) = make_float4(uo[0],uo[1],uo[2],uo[3]);
    if (wout)
        *(float4*)(out + (size_t)b*NPIX + dgidx) = make_float4(ao[0],ao[1],ao[2],ao[3]);

    moments3_reduce(s0, sy, syy, i0, g_sums[(t+1)%3][b], rowred, tid);
}

__global__ __launch_bounds__(256, 5) void step_kernel(const float* __restrict__ o,
                                                      float* __restrict__ out, int t)
{
    __shared__ float u_s[36][40];
    __shared__ float q_s[34][40];
    __shared__ float t_s[36][36];
    __shared__ float txq_s[33][36];
    __shared__ float tyq_s[33][36];
    __shared__ float sc[5];
    __shared__ float rowred[32][3];

    int tid = threadIdx.x;
    int b  = blockIdx.z;
    int i0 = blockIdx.y * 32, j0 = blockIdx.x * 32;

    const float* u_in  = g_u[t & 1]     + (size_t)b * NPIX;
    const float* q_in  = g_q[t & 1]     + (size_t)b * NPIX;
    float*       u_out = g_u[(t+1) & 1] + (size_t)b * NPIX;
    float*       q_out = g_q[(t+1) & 1] + (size_t)b * NPIX;
    const float* ob    = o              + (size_t)b * NPIX;

    // Block-uniform branch: tile needs no border handling anywhere.
    bool interior = (blockIdx.x > 0) & (blockIdx.x < 15) &
                    (blockIdx.y > 0) & (blockIdx.y < 15);
    if (interior)
        step_impl<true >(ob, u_in, q_in, u_out, q_out, out, b, i0, j0, tid, t,
                         u_s, q_s, t_s, txq_s, tyq_s, sc, rowred);
    else
        step_impl<false>(ob, u_in, q_in, u_out, q_out, out, b, i0, j0, tid, t,
                         u_s, q_s, t_s, txq_s, tyq_s, sc, rowred);
}

extern "C" void kernel_launch(void* const* d_in, const int* in_sizes, int n_in,
                              void* d_out, int out_size) {
    const float* o = (const float*)d_in[0];
    float* out = (float*)d_out;
    (void)in_sizes; (void)n_in; (void)out_size;

    dim3 grid(WW/32, HH/32, BB);

    zero_sums_kernel<<<1, 256>>>();
    init_kernel<<<grid, 256>>>(o);
    for (int t = 0; t < ITERS; t++)
        step_kernel<<<grid, 256>>>(o, (t == ITERS-1) ? out : nullptr, t);
}

// round 16
// speedup vs baseline: 1.6952x; 1.0059x over previous
#include <cuda_runtime.h>
#include <cstdint>

#define HH 512
#define WW 512
#define BB 8
#define NPIX (HH*WW)
#define ITERS 50
#define CC 256.5f

// Double-buffered state + triple-buffered moment sums (zero/accum/read rotate).
__device__ float  g_u[2][BB*NPIX];
__device__ float  g_q[2][BB*NPIX];
__device__ double g_sums[3][BB][8];

// PDL: wait until the previous grid (programmatic-serialized) completes.
__device__ __forceinline__ void gdc_wait() {
    asm volatile("griddepcontrol.wait;" ::: "memory");
}

__global__ void zero_sums_kernel() {
    int i = threadIdx.x;
    if (i < 3*BB*8) reinterpret_cast<double*>(g_sums)[i] = 0.0;
}

__device__ __forceinline__ float sigmoid_fast(float x) {
    float t;
    asm("tanh.approx.f32 %0, %1;" : "=f"(t) : "f"(0.5f * x));
    return fmaf(0.5f, t, 0.5f);
}

// Two-stage moment reduction. tid = row*8 + colgroup, so the 8 lanes of a row
// share xc: reduce (s0,sy,syy) over them (9 SHFL), park row triples in smem.
// Barrier is split: warps 1-7 arrive and exit; only warp 0 waits and finishes.
__device__ __forceinline__ void moments3_reduce(float s0, float sy, float syy,
                                                int i0, double* dst,
                                                float (*rowred)[3], int tid) {
#pragma unroll
    for (int off = 1; off <= 4; off <<= 1) {
        s0  += __shfl_xor_sync(0xffffffffu, s0,  off);
        sy  += __shfl_xor_sync(0xffffffffu, sy,  off);
        syy += __shfl_xor_sync(0xffffffffu, syy, off);
    }
    if ((tid & 7) == 0) {
        int r = tid >> 3;
        rowred[r][0] = s0; rowred[r][1] = sy; rowred[r][2] = syy;
    }
    if (tid < 32) {
        asm volatile("bar.sync 1, 256;" ::: "memory");   // wait for all arrivals
        float a0 = rowred[tid][0], a1 = rowred[tid][1], a2 = rowred[tid][2];
        float xc = (float)(i0 + tid + 1) - CC;
        float m[6] = { a0, xc*a0, a1, xc*xc*a0, a2, xc*a1 };
#pragma unroll
        for (int off = 16; off; off >>= 1)
#pragma unroll
            for (int k = 0; k < 6; k++) m[k] += __shfl_xor_sync(0xffffffffu, m[k], off);
        if (tid == 0)
#pragma unroll
            for (int k = 0; k < 6; k++) atomicAdd(&dst[k], (double)m[k]);
    } else {
        asm volatile("bar.arrive 1, 256;" ::: "memory"); // no wait; warp may exit
    }
}

// u0 = sigmoid(o), q0 = 0, moments(u0) -> g_sums[0]. 4 px / thread, float4 I/O.
__global__ __launch_bounds__(256) void init_kernel(const float* __restrict__ o) {
    int tid = threadIdx.x;
    int b  = blockIdx.z;
    int i0 = blockIdx.y * 32, j0 = blockIdx.x * 32;
    int i = tid >> 3, j = (tid & 7) * 4;
    int gi = i0 + i, gj = j0 + j;
    int gidx = gi*WW + gj;
    const float* ob = o + (size_t)b * NPIX;

    float4 ov = *(const float4*)(ob + gidx);   // o is kernel-independent input
    gdc_wait();   // zero_sums must have zeroed g_sums before our atomics below

    float un[4];
    un[0] = sigmoid_fast(ov.x);
    un[1] = sigmoid_fast(ov.y);
    un[2] = sigmoid_fast(ov.z);
    un[3] = sigmoid_fast(ov.w);
    *(float4*)(g_u[0] + (size_t)b*NPIX + gidx) = make_float4(un[0],un[1],un[2],un[3]);
    *(float4*)(g_q[0] + (size_t)b*NPIX + gidx) = make_float4(0.f,0.f,0.f,0.f);

    float s0 = 0.f, sy = 0.f, syy = 0.f;
#pragma unroll
    for (int k = 0; k < 4; k++) {
        float yc = (float)(gj+k+1) - CC;
        s0 += un[k]; sy += un[k]*yc; syy += un[k]*yc*yc;
    }
    __shared__ float rowred[32][3];
    moments3_reduce(s0, sy, syy, i0, g_sums[0][b], rowred, tid);
}

// One full iteration. INTERIOR=true: tile touches no image border -> all
// bounds checks and border-mass corrections compile out.
template<bool INTERIOR>
__device__ __forceinline__ void step_impl(
    const float* __restrict__ ob, const float* __restrict__ u_in,
    const float* __restrict__ q_in, float* __restrict__ u_out,
    float* __restrict__ q_out, float* __restrict__ out,
    int b, int i0, int j0, int tid, int t,
    float (*u_s)[40], float (*q_s)[40], float (*t_s)[36],
    float (*txq_s)[36], float (*tyq_s)[36], float* sc, float (*rowred)[3])
{
    // Output strip coords (also used to prefetch o before the first sync).
    int di = tid >> 3, dj = (tid & 7) * 4;
    int dgi = i0 + di, dgj0 = j0 + dj;
    int dgidx = dgi*WW + dgj0;
    float4 ov = *(const float4*)(ob + dgidx);   // prefetch: independent of prior kernel

    // PDL gate: everything below reads/writes state owned by the previous kernel
    // (u_in/q_in/g_sums reads; u_out/q_out writes race with its q_in/u_in reads).
    gdc_wait();

    // Zero the sums buffer used two iterations from now.
    if (blockIdx.x == 0 && blockIdx.y == 0 && b == 0 && tid < BB*8)
        reinterpret_cast<double*>(g_sums[(t+2)%3])[tid] = 0.0;

    if (tid == 0) {  // scalars from fp64 moments (centered at CC)
        const double* S = g_sums[t % 3][b];
        double inv = 1.0 / S[0];
        double dx = S[1]*inv, dy = S[2]*inv;
        sc[0] = (float)dx; sc[1] = (float)dy;
        sc[2] = (float)(S[5]*inv - dx*dy);   // cossin
        sc[3] = (float)(S[3]*inv - dx*dx);   // bsin
        sc[4] = (float)(S[4]*inv - dy*dy);   // asin
    }

    // ---- Phase A: tile loads (u: 36x10 vec4 = 360 items, q: 34x10 = 340).
    // Interior path is straight-line with all LDGs issued before any STS (MLP=3).
    if (INTERIOR) {
        // item 0: always u (idx = tid in [0,360))
        int r0 = tid / 10, c0 = tid - r0*10;
        const float* p0 = u_in + (i0 + r0 - 2)*WW + (j0 + 4*c0 - 4);
        // item 1: u if tid<104 (idx=tid+256<360), else q (k = tid-104)
        bool l1u = tid < 104;
        int k1 = l1u ? tid + 256 : tid - 104;
        int r1 = k1 / 10, c1 = k1 - r1*10;
        const float* p1 = (l1u ? u_in + (i0 + r1 - 2)*WW
                               : q_in + (i0 + r1 - 1)*WW) + (j0 + 4*c1 - 4);
        // item 2: q (k = tid+152), valid while tid<188
        bool has2 = tid < 188;
        int k2 = tid + 152;
        int r2 = k2 / 10, c2 = k2 - r2*10;
        const float* p2 = q_in + (i0 + r2 - 1)*WW + (j0 + 4*c2 - 4);

        float4 v0 = *(const float4*)p0;
        float4 v1 = *(const float4*)p1;
        float4 v2 = make_float4(0.f,0.f,0.f,0.f);
        if (has2) v2 = *(const float4*)p2;

        *(float4*)&u_s[r0][4*c0] = v0;
        if (l1u) *(float4*)&u_s[r1][4*c1] = v1;
        else     *(float4*)&q_s[r1][4*c1] = v1;
        if (has2) *(float4*)&q_s[r2][4*c2] = v2;
    } else {
#pragma unroll
        for (int s = 0; s < 3; s++) {
            int idx = tid + 256*s;
            if (idx < 700) {
                bool isq = idx >= 360;
                int k = isq ? idx - 360 : idx;
                int r = k / 10, c = k - r*10;
                int gi = i0 + r - (isq ? 1 : 2);
                int gj = j0 + 4*c - 4;
                float4 v = make_float4(0.f,0.f,0.f,0.f);
                if ((unsigned)gi < HH && (unsigned)gj < WW)
                    v = *(const float4*)((isq ? q_in : u_in) + gi*WW + gj);
                if (isq) *(float4*)&q_s[r][4*c] = v;
                else     *(float4*)&u_s[r][4*c] = v;
            }
        }
    }
    __syncthreads();

    float dofx = sc[0], dofy = sc[1], cossin = sc[2], bsin = sc[3], asin_ = sc[4];

    // Normalized separable gaussian weights g(a)=exp(-a^2/50)/S.
    float e1 = __expf(-0.02f), e2 = __expf(-0.08f);
    float invs = 1.f / (1.f + 2.f*(e1 + e2));
    float w0 = e2*invs, w1 = e1*invs, w2 = invs;

    // ---- Phase B: gaussian column pass, 36 rows x 8 vec4 groups ----
#pragma unroll
    for (int s = 0; s < 2; s++) {
        int idx = tid + 256*s;
        if (idx < 288) {
            int r = idx >> 3, x = idx & 7;
            int g0 = 4*x;
            float4 a = *(float4*)&u_s[r][g0];
            float4 bb = *(float4*)&u_s[r][g0+4];
            float4 cc = *(float4*)&u_s[r][g0+8];
            float e[12] = {a.x,a.y,a.z,a.w, bb.x,bb.y,bb.z,bb.w, cc.x,cc.y,cc.z,cc.w};
            float4 ot;
            ot.x = w0*(e[2]+e[6]) + w1*(e[3]+e[5]) + w2*e[4];
            ot.y = w0*(e[3]+e[7]) + w1*(e[4]+e[6]) + w2*e[5];
            ot.z = w0*(e[4]+e[8]) + w1*(e[5]+e[7]) + w2*e[6];
            ot.w = w0*(e[5]+e[9]) + w1*(e[6]+e[8]) + w2*e[7];
            *(float4*)&t_s[r][g0] = ot;
        }
    }

    // ---- Phase C: q_new / Tx*q / Ty*q over halo-1 region (33 rows x 9 vec4).
    // q_new for in-tile pixels goes straight to q_out.
#pragma unroll
    for (int s = 0; s < 2; s++) {
        int idx = tid + 256*s;
        if (idx < 297) {
            int r = idx / 9, c = idx - r*9;
            int m0 = 4*c;
            int gi = i0 - 1 + r;
            float4 ca = *(float4*)&u_s[r+1][m0];
            float4 cb = *(float4*)&u_s[r+1][m0+4];
            float4 da = *(float4*)&u_s[r+2][m0];
            float4 db = *(float4*)&u_s[r+2][m0+4];
            float4 qa = *(float4*)&q_s[r][m0];
            float4 qb = *(float4*)&q_s[r][m0+4];
            float uc[4] = {ca.z, ca.w, cb.x, cb.y};   // u(i,j)
            float ur[4] = {ca.w, cb.x, cb.y, cb.z};   // u(i,j+1)
            float ud[4] = {da.z, da.w, db.x, db.y};   // u(i+1,j)
            float qq[4] = {qa.z, qa.w, qb.x, qb.y};
            float dxv = (float)(gi+1) - CC - dofx;
            int gj0c = j0 + m0 - 2;
            // Incremental Tx/Ty: d/dk Tx = bsin, d/dk Ty = cossin.
            float dyv0 = (float)(gj0c+1) - CC - dofy;
            float Txk = dyv0*bsin   - dxv*cossin;
            float Tyk = dyv0*cossin - dxv*asin_;
            float rtx[4], rty[4], rqn[4];
#pragma unroll
            for (int k = 0; k < 4; k++) {
                float inv = rsqrtf(fmaf(Txk, Txk, Tyk*Tyk) + 1e-20f);
                float nx = Txk*inv, ny = Tyk*inv;
                float qn = qq[k] - ((ud[k]-uc[k])*nx + (ur[k]-uc[k])*ny);  // TAU=1
                if (!INTERIOR) {
                    bool ok = (gi >= 0) && ((unsigned)(gj0c + k) < WW);
                    qn = ok ? qn : 0.f;
                }
                rqn[k] = qn; rtx[k] = nx*qn; rty[k] = ny*qn;
                Txk += bsin; Tyk += cossin;
            }
            *(float4*)&txq_s[r][m0] = make_float4(rtx[0],rtx[1],rtx[2],rtx[3]);
            *(float4*)&tyq_s[r][m0] = make_float4(rty[0],rty[1],rty[2],rty[3]);
            if (r >= 1) {
#pragma unroll
                for (int k = 0; k < 4; k++) {
                    int lj = m0 + k - 2;
                    if ((unsigned)lj < 32u) q_out[gi*WW + j0 + lj] = rqn[k];
                }
            }
        }
    }
    __syncthreads();

    // ---- Phase D: output, 1 vec4 strip per thread ----
    int i = di, j = dj;
    float4 t0 = *(float4*)&t_s[i  ][j];
    float4 t1 = *(float4*)&t_s[i+1][j];
    float4 t2 = *(float4*)&t_s[i+2][j];
    float4 t3 = *(float4*)&t_s[i+3][j];
    float4 t4 = *(float4*)&t_s[i+4][j];
    float ta[4] = {t0.x,t0.y,t0.z,t0.w};
    float tb[4] = {t1.x,t1.y,t1.z,t1.w};
    float tc[4] = {t2.x,t2.y,t2.z,t2.w};
    float td[4] = {t3.x,t3.y,t3.z,t3.w};
    float te[4] = {t4.x,t4.y,t4.z,t4.w};

    float4 A0 = *(float4*)&txq_s[i+1][j], A1 = *(float4*)&txq_s[i+1][j+4];
    float4 B0 = *(float4*)&txq_s[i  ][j], B1 = *(float4*)&txq_s[i  ][j+4];
    float4 Y0 = *(float4*)&tyq_s[i+1][j], Y1 = *(float4*)&tyq_s[i+1][j+4];
    float ax[8] = {A0.x,A0.y,A0.z,A0.w, A1.x,A1.y,A1.z,A1.w};
    float bx[8] = {B0.x,B0.y,B0.z,B0.w, B1.x,B1.y,B1.z,B1.w};
    float yx[8] = {Y0.x,Y0.y,Y0.z,Y0.w, Y1.x,Y1.y,Y1.z,Y1.w};

    float oo[4] = {ov.x, ov.y, ov.z, ov.w};

    // row border mass for p = conv(1-2u)
    float ra = 1.f;
    if (!INTERIOR) {
        if (dgi == 0) ra -= w0 + w1; else if (dgi == 1) ra -= w0;
        if (dgi == HH-1) ra -= w0 + w1; else if (dgi == HH-2) ra -= w0;
    }

    float s0 = 0.f, sy = 0.f, syy = 0.f;
    float uo[4], ao[4];
    bool wout = (out != nullptr);
#pragma unroll
    for (int k = 0; k < 4; k++) {
        float Tq = ax[k+2] - bx[k+2] + yx[k+2] - yx[k+1];
        float conv = w0*(ta[k]+te[k]) + w1*(tb[k]+td[k]) + w2*tc[k];
        float p;
        if (INTERIOR) {
            p = 1.f - 2.f*conv;
        } else {
            int gj = dgj0 + k;
            float rb = 1.f;
            if (gj == 0) rb -= w0 + w1; else if (gj == 1) rb -= w0;
            if (gj == WW-1) rb -= w0 + w1; else if (gj == WW-2) rb -= w0;
            p = ra*rb - 2.f*conv;
        }
        float arg = oo[k] - p - Tq;          // LAM = EPS = 1
        float un  = sigmoid_fast(arg);
        uo[k] = un; ao[k] = arg;
        float yc = (float)(dgj0+k+1) - CC;
        s0 += un; sy += un*yc; syy += un*yc*yc;
    }
    *(float4*)(u_out + dgidx) = make_float4(uo[0],uo[1],uo[2],uo[3]);
    if (wout)
        *(float4*)(out + (size_t)b*NPIX + dgidx) = make_float4(ao[0],ao[1],ao[2],ao[3]);

    moments3_reduce(s0, sy, syy, i0, g_sums[(t+1)%3][b], rowred, tid);
}

__global__ __launch_bounds__(256, 5) void step_kernel(const float* __restrict__ o,
                                                      float* __restrict__ out, int t)
{
    __shared__ float u_s[36][40];
    __shared__ float q_s[34][40];
    __shared__ float t_s[36][36];
    __shared__ float txq_s[33][36];
    __shared__ float tyq_s[33][36];
    __shared__ float sc[5];
    __shared__ float rowred[32][3];

    int tid = threadIdx.x;
    int b  = blockIdx.z;
    int i0 = blockIdx.y * 32, j0 = blockIdx.x * 32;

    const float* u_in  = g_u[t & 1]     + (size_t)b * NPIX;
    const float* q_in  = g_q[t & 1]     + (size_t)b * NPIX;
    float*       u_out = g_u[(t+1) & 1] + (size_t)b * NPIX;
    float*       q_out = g_q[(t+1) & 1] + (size_t)b * NPIX;
    const float* ob    = o              + (size_t)b * NPIX;

    // Block-uniform branch: tile needs no border handling anywhere.
    bool interior = (blockIdx.x > 0) & (blockIdx.x < 15) &
                    (blockIdx.y > 0) & (blockIdx.y < 15);
    if (interior)
        step_impl<true >(ob, u_in, q_in, u_out, q_out, out, b, i0, j0, tid, t,
                         u_s, q_s, t_s, txq_s, tyq_s, sc, rowred);
    else
        step_impl<false>(ob, u_in, q_in, u_out, q_out, out, b, i0, j0, tid, t,
                         u_s, q_s, t_s, txq_s, tyq_s, sc, rowred);
}

extern "C" void kernel_launch(void* const* d_in, const int* in_sizes, int n_in,
                              void* d_out, int out_size) {
    const float* o = (const float*)d_in[0];
    float* out = (float*)d_out;
    (void)in_sizes; (void)n_in; (void)out_size;

    dim3 grid(WW/32, HH/32, BB);

    zero_sums_kernel<<<1, 256>>>();

    // PDL: allow each kernel's launch machinery + o-prefetch to overlap the
    // previous kernel's tail; griddepcontrol.wait in-kernel preserves ordering.
    cudaLaunchAttribute attr[1];
    attr[0].id = cudaLaunchAttributeProgrammaticStreamSerialization;
    attr[0].val.programmaticStreamSerializationAllowed = 1;

    {
        cudaLaunchConfig_t cfg = {};
        cfg.gridDim = grid; cfg.blockDim = dim3(256,1,1);
        cfg.stream = 0; cfg.attrs = attr; cfg.numAttrs = 1;
        cudaLaunchKernelEx(&cfg, init_kernel, o);
    }
    for (int t = 0; t < ITERS; t++) {
        cudaLaunchConfig_t cfg = {};
        cfg.gridDim = grid; cfg.blockDim = dim3(256,1,1);
        cfg.stream = 0; cfg.attrs = attr; cfg.numAttrs = 1;
        float* op = (t == ITERS-1) ? out : nullptr;
        cudaLaunchKernelEx(&cfg, step_kernel, o, op, t);
    }
}

// round 17
// speedup vs baseline: 1.8089x; 1.0671x over previous
#include <cuda_runtime.h>
#include <cstdint>

#define HH 512
#define WW 512
#define BB 8
#define NPIX (HH*WW)
#define ITERS 50
#define CC 256.5f

typedef unsigned long long u64;

// Double-buffered state + triple-buffered moment sums (zero/accum/read rotate).
__device__ float  g_u[2][BB*NPIX];
__device__ float  g_q[2][BB*NPIX];
__device__ double g_sums[3][BB][8];

// ---- packed f32x2 helpers (lanewise on (lo,hi) pairs) ----
__device__ __forceinline__ u64 pk2(float lo, float hi) {
    u64 r; asm("mov.b64 %0,{%1,%2};" : "=l"(r) : "f"(lo), "f"(hi)); return r;
}
__device__ __forceinline__ void upk2(u64 v, float& lo, float& hi) {
    asm("mov.b64 {%0,%1},%2;" : "=f"(lo), "=f"(hi) : "l"(v));
}
__device__ __forceinline__ u64 add2(u64 a, u64 b) {
    u64 r; asm("add.rn.f32x2 %0,%1,%2;" : "=l"(r) : "l"(a), "l"(b)); return r;
}
__device__ __forceinline__ u64 mul2(u64 a, u64 b) {
    u64 r; asm("mul.rn.f32x2 %0,%1,%2;" : "=l"(r) : "l"(a), "l"(b)); return r;
}
__device__ __forceinline__ u64 fma2(u64 a, u64 b, u64 c) {
    u64 r; asm("fma.rn.f32x2 %0,%1,%2,%3;" : "=l"(r) : "l"(a), "l"(b), "l"(c)); return r;
}
// a - b, via single-rounded fma(b, -1, a)
__device__ __forceinline__ u64 sub2(u64 a, u64 b, u64 m1) { return fma2(b, m1, a); }

// PDL: wait until the previous grid (programmatic-serialized) completes.
__device__ __forceinline__ void gdc_wait() {
    asm volatile("griddepcontrol.wait;" ::: "memory");
}

__global__ void zero_sums_kernel() {
    int i = threadIdx.x;
    if (i < 3*BB*8) reinterpret_cast<double*>(g_sums)[i] = 0.0;
}

__device__ __forceinline__ float sigmoid_fast(float x) {
    float t;
    asm("tanh.approx.f32 %0, %1;" : "=f"(t) : "f"(0.5f * x));
    return fmaf(0.5f, t, 0.5f);
}

// Two-stage moment reduction. tid = row*8 + colgroup, so the 8 lanes of a row
// share xc: reduce (s0,sy,syy) over them (9 SHFL), park row triples in smem.
// Barrier is split: warps 1-7 arrive and exit; only warp 0 waits and finishes.
__device__ __forceinline__ void moments3_reduce(float s0, float sy, float syy,
                                                int i0, double* dst,
                                                float (*rowred)[3], int tid) {
#pragma unroll
    for (int off = 1; off <= 4; off <<= 1) {
        s0  += __shfl_xor_sync(0xffffffffu, s0,  off);
        sy  += __shfl_xor_sync(0xffffffffu, sy,  off);
        syy += __shfl_xor_sync(0xffffffffu, syy, off);
    }
    if ((tid & 7) == 0) {
        int r = tid >> 3;
        rowred[r][0] = s0; rowred[r][1] = sy; rowred[r][2] = syy;
    }
    if (tid < 32) {
        asm volatile("bar.sync 1, 256;" ::: "memory");   // wait for all arrivals
        float a0 = rowred[tid][0], a1 = rowred[tid][1], a2 = rowred[tid][2];
        float xc = (float)(i0 + tid + 1) - CC;
        float m[6] = { a0, xc*a0, a1, xc*xc*a0, a2, xc*a1 };
#pragma unroll
        for (int off = 16; off; off >>= 1)
#pragma unroll
            for (int k = 0; k < 6; k++) m[k] += __shfl_xor_sync(0xffffffffu, m[k], off);
        if (tid == 0)
#pragma unroll
            for (int k = 0; k < 6; k++) atomicAdd(&dst[k], (double)m[k]);
    } else {
        asm volatile("bar.arrive 1, 256;" ::: "memory"); // no wait; warp may exit
    }
}

// u0 = sigmoid(o), q0 = 0, moments(u0) -> g_sums[0]. 4 px / thread, float4 I/O.
__global__ __launch_bounds__(256) void init_kernel(const float* __restrict__ o) {
    int tid = threadIdx.x;
    int b  = blockIdx.z;
    int i0 = blockIdx.y * 32, j0 = blockIdx.x * 32;
    int i = tid >> 3, j = (tid & 7) * 4;
    int gi = i0 + i, gj = j0 + j;
    int gidx = gi*WW + gj;
    const float* ob = o + (size_t)b * NPIX;

    float4 ov = *(const float4*)(ob + gidx);   // o is kernel-independent input
    gdc_wait();   // zero_sums must have zeroed g_sums before our atomics below

    float un[4];
    un[0] = sigmoid_fast(ov.x);
    un[1] = sigmoid_fast(ov.y);
    un[2] = sigmoid_fast(ov.z);
    un[3] = sigmoid_fast(ov.w);
    *(float4*)(g_u[0] + (size_t)b*NPIX + gidx) = make_float4(un[0],un[1],un[2],un[3]);
    *(float4*)(g_q[0] + (size_t)b*NPIX + gidx) = make_float4(0.f,0.f,0.f,0.f);

    float s0 = 0.f, sy = 0.f, syy = 0.f;
#pragma unroll
    for (int k = 0; k < 4; k++) {
        float yc = (float)(gj+k+1) - CC;
        s0 += un[k]; sy += un[k]*yc; syy += un[k]*yc*yc;
    }
    __shared__ float rowred[32][3];
    moments3_reduce(s0, sy, syy, i0, g_sums[0][b], rowred, tid);
}

// One full iteration. INTERIOR=true: tile touches no image border -> all
// bounds checks and border-mass corrections compile out.
template<bool INTERIOR>
__device__ __forceinline__ void step_impl(
    const float* __restrict__ ob, const float* __restrict__ u_in,
    const float* __restrict__ q_in, float* __restrict__ u_out,
    float* __restrict__ q_out, float* __restrict__ out,
    int b, int i0, int j0, int tid, int t,
    float (*u_s)[40], float (*q_s)[40], float (*t_s)[36],
    float (*txq_s)[36], float (*tyq_s)[36], float* sc, float (*rowred)[3])
{
    // Output strip coords (also used to prefetch o before the first sync).
    int di = tid >> 3, dj = (tid & 7) * 4;
    int dgi = i0 + di, dgj0 = j0 + dj;
    int dgidx = dgi*WW + dgj0;
    ulonglong2 ovp = *(const ulonglong2*)(ob + dgidx);  // prefetch, packed pairs

    // PDL gate: everything below reads/writes state owned by the previous kernel.
    gdc_wait();

    // Zero the sums buffer used two iterations from now.
    if (blockIdx.x == 0 && blockIdx.y == 0 && b == 0 && tid < BB*8)
        reinterpret_cast<double*>(g_sums[(t+2)%3])[tid] = 0.0;

    if (tid == 0) {  // scalars from fp64 moments; divides in fp32 (short chain)
        const double* S = g_sums[t % 3][b];
        float S0=(float)S[0], S1=(float)S[1], S2=(float)S[2];
        float S3=(float)S[3], S4=(float)S[4], S5=(float)S[5];
        float inv = __fdividef(1.0f, S0);
        float dx = S1*inv, dy = S2*inv;
        sc[0] = dx; sc[1] = dy;
        sc[2] = fmaf(-dx, dy, S5*inv);   // cossin
        sc[3] = fmaf(-dx, dx, S3*inv);   // bsin
        sc[4] = fmaf(-dy, dy, S4*inv);   // asin
    }

    // ---- Phase A: tile loads (u: 36x10 vec4 = 360 items, q: 33x10 = 330).
    // Interior path is straight-line with all LDGs issued before any STS (MLP=3).
    if (INTERIOR) {
        // item 0: always u (idx = tid in [0,360))
        int r0 = tid / 10, c0 = tid - r0*10;
        const float* p0 = u_in + (i0 + r0 - 2)*WW + (j0 + 4*c0 - 4);
        // item 1: u if tid<104 (idx=tid+256<360), else q (k = tid-104)
        bool l1u = tid < 104;
        int k1 = l1u ? tid + 256 : tid - 104;
        int r1 = k1 / 10, c1 = k1 - r1*10;
        const float* p1 = (l1u ? u_in + (i0 + r1 - 2)*WW
                               : q_in + (i0 + r1 - 1)*WW) + (j0 + 4*c1 - 4);
        // item 2: q (k = tid+152), valid while tid<178 (k<330)
        bool has2 = tid < 178;
        int k2 = tid + 152;
        int r2 = k2 / 10, c2 = k2 - r2*10;
        const float* p2 = q_in + (i0 + r2 - 1)*WW + (j0 + 4*c2 - 4);

        float4 v0 = *(const float4*)p0;
        float4 v1 = *(const float4*)p1;
        float4 v2 = make_float4(0.f,0.f,0.f,0.f);
        if (has2) v2 = *(const float4*)p2;

        *(float4*)&u_s[r0][4*c0] = v0;
        if (l1u) *(float4*)&u_s[r1][4*c1] = v1;
        else     *(float4*)&q_s[r1][4*c1] = v1;
        if (has2) *(float4*)&q_s[r2][4*c2] = v2;
    } else {
#pragma unroll
        for (int s = 0; s < 3; s++) {
            int idx = tid + 256*s;
            if (idx < 690) {
                bool isq = idx >= 360;
                int k = isq ? idx - 360 : idx;
                int r = k / 10, c = k - r*10;
                int gi = i0 + r - (isq ? 1 : 2);
                int gj = j0 + 4*c - 4;
                float4 v = make_float4(0.f,0.f,0.f,0.f);
                if ((unsigned)gi < HH && (unsigned)gj < WW)
                    v = *(const float4*)((isq ? q_in : u_in) + gi*WW + gj);
                if (isq) *(float4*)&q_s[r][4*c] = v;
                else     *(float4*)&u_s[r][4*c] = v;
            }
        }
    }
    __syncthreads();

    float dofx = sc[0], dofy = sc[1], cossin = sc[2], bsin = sc[3], asin_ = sc[4];

    // Normalized separable gaussian weights g(a)=exp(-a^2/50)/S.
    float e1 = __expf(-0.02f), e2 = __expf(-0.08f);
    float invs = 1.f / (1.f + 2.f*(e1 + e2));
    float w0 = e2*invs, w1 = e1*invs, w2 = invs;

    // ---- Phase B: gaussian column pass, 36 rows x 8 vec4 groups ----
#pragma unroll
    for (int s = 0; s < 2; s++) {
        int idx = tid + 256*s;
        if (idx < 288) {
            int r = idx >> 3, x = idx & 7;
            int g0 = 4*x;
            float4 a = *(float4*)&u_s[r][g0];
            float4 bb = *(float4*)&u_s[r][g0+4];
            float4 cc = *(float4*)&u_s[r][g0+8];
            float e[12] = {a.x,a.y,a.z,a.w, bb.x,bb.y,bb.z,bb.w, cc.x,cc.y,cc.z,cc.w};
            float4 ot;
            ot.x = w0*(e[2]+e[6]) + w1*(e[3]+e[5]) + w2*e[4];
            ot.y = w0*(e[3]+e[7]) + w1*(e[4]+e[6]) + w2*e[5];
            ot.z = w0*(e[4]+e[8]) + w1*(e[5]+e[7]) + w2*e[6];
            ot.w = w0*(e[5]+e[9]) + w1*(e[6]+e[8]) + w2*e[7];
            *(float4*)&t_s[r][g0] = ot;
        }
    }

    // ---- Phase C: q_new / Tx*q / Ty*q over halo-1 region (33 rows x 9 vec4).
    // q_new for in-tile pixels goes straight to q_out.
#pragma unroll
    for (int s = 0; s < 2; s++) {
        int idx = tid + 256*s;
        if (idx < 297) {
            int r = idx / 9, c = idx - r*9;
            int m0 = 4*c;
            int gi = i0 - 1 + r;
            float4 ca = *(float4*)&u_s[r+1][m0];
            float4 cb = *(float4*)&u_s[r+1][m0+4];
            float4 da = *(float4*)&u_s[r+2][m0];
            float4 db = *(float4*)&u_s[r+2][m0+4];
            float4 qa = *(float4*)&q_s[r][m0];
            float4 qb = *(float4*)&q_s[r][m0+4];
            float uc[4] = {ca.z, ca.w, cb.x, cb.y};   // u(i,j)
            float ur[4] = {ca.w, cb.x, cb.y, cb.z};   // u(i,j+1)
            float ud[4] = {da.z, da.w, db.x, db.y};   // u(i+1,j)
            float qq[4] = {qa.z, qa.w, qb.x, qb.y};
            float dxv = (float)(gi+1) - CC - dofx;
            int gj0c = j0 + m0 - 2;
            // Incremental Tx/Ty: d/dk Tx = bsin, d/dk Ty = cossin.
            float dyv0 = (float)(gj0c+1) - CC - dofy;
            float Txk = dyv0*bsin   - dxv*cossin;
            float Tyk = dyv0*cossin - dxv*asin_;
            float rtx[4], rty[4], rqn[4];
#pragma unroll
            for (int k = 0; k < 4; k++) {
                float inv = rsqrtf(fmaf(Txk, Txk, Tyk*Tyk) + 1e-20f);
                float nx = Txk*inv, ny = Tyk*inv;
                float qn = qq[k] - ((ud[k]-uc[k])*nx + (ur[k]-uc[k])*ny);  // TAU=1
                if (!INTERIOR) {
                    bool ok = (gi >= 0) && ((unsigned)(gj0c + k) < WW);
                    qn = ok ? qn : 0.f;
                }
                rqn[k] = qn; rtx[k] = nx*qn; rty[k] = ny*qn;
                Txk += bsin; Tyk += cossin;
            }
            *(float4*)&txq_s[r][m0] = make_float4(rtx[0],rtx[1],rtx[2],rtx[3]);
            *(float4*)&tyq_s[r][m0] = make_float4(rty[0],rty[1],rty[2],rty[3]);
            if (r >= 1) {
#pragma unroll
                for (int k = 0; k < 4; k++) {
                    int lj = m0 + k - 2;
                    if ((unsigned)lj < 32u) q_out[gi*WW + j0 + lj] = rqn[k];
                }
            }
        }
    }
    __syncthreads();

    // ---- Phase D: output, 1 vec4 strip per thread; packed f32x2 math ----
    int i = di, j = dj;
    const ulonglong2 t0 = *(const ulonglong2*)&t_s[i  ][j];
    const ulonglong2 t1 = *(const ulonglong2*)&t_s[i+1][j];
    const ulonglong2 t2 = *(const ulonglong2*)&t_s[i+2][j];
    const ulonglong2 t3 = *(const ulonglong2*)&t_s[i+3][j];
    const ulonglong2 t4 = *(const ulonglong2*)&t_s[i+4][j];
    const ulonglong2 a0 = *(const ulonglong2*)&txq_s[i+1][j];
    const u64        a45 = *(const u64*)&txq_s[i+1][j+4];
    const ulonglong2 b0 = *(const ulonglong2*)&txq_s[i  ][j];
    const u64        b45 = *(const u64*)&txq_s[i  ][j+4];
    const ulonglong2 y0 = *(const ulonglong2*)&tyq_s[i+1][j];
    const u64        y45 = *(const u64*)&tyq_s[i+1][j+4];

    const u64 M1  = pk2(-1.f, -1.f);
    const u64 W0p = pk2(w0, w0), W1p = pk2(w1, w1), W2p = pk2(w2, w2);

    // conv pairs (column-pass rows i..i+4 combined with row weights)
    u64 conv01 = fma2(W2p, t2.x,
                  fma2(W1p, add2(t1.x, t3.x),
                   mul2(W0p, add2(t0.x, t4.x))));
    u64 conv23 = fma2(W2p, t2.y,
                  fma2(W1p, add2(t1.y, t3.y),
                   mul2(W0p, add2(t0.y, t4.y))));

    // Tq pairs: (txq(i)-txq(i-1)) + (tyq(i,j)-tyq(i,j-1))
    float yf0, yf1, yf2, yf3, yf4, yf5;
    upk2(y0.x, yf0, yf1); upk2(y0.y, yf2, yf3); upk2(y45, yf4, yf5);
    u64 yx12 = pk2(yf1, yf2), yx34 = pk2(yf3, yf4);
    u64 Tq01 = add2(sub2(a0.y, b0.y, M1), sub2(y0.y, yx12, M1));
    u64 Tq23 = add2(sub2(a45,  b45,  M1), sub2(y45,  yx34, M1));

    float s0 = 0.f, sy = 0.f, syy = 0.f;
    float uo[4], ao[4];
    bool wout = (out != nullptr);

    if (INTERIOR) {
        // arg = (oo - 1) + 2*conv - Tq
        const u64 ONEp = pk2(1.f, 1.f), TWOp = pk2(2.f, 2.f);
        u64 g01 = sub2(fma2(TWOp, conv01, sub2(ovp.x, ONEp, M1)), Tq01, M1);
        u64 g23 = sub2(fma2(TWOp, conv23, sub2(ovp.y, ONEp, M1)), Tq23, M1);
        upk2(g01, ao[0], ao[1]); upk2(g23, ao[2], ao[3]);
#pragma unroll
        for (int k = 0; k < 4; k++) {
            float un = sigmoid_fast(ao[k]);
            uo[k] = un;
            float yc = (float)(dgj0+k+1) - CC;
            s0 += un; sy += un*yc; syy += un*yc*yc;
        }
    } else {
        float convs[4], Tqs[4], oos[4];
        upk2(conv01, convs[0], convs[1]); upk2(conv23, convs[2], convs[3]);
        upk2(Tq01, Tqs[0], Tqs[1]);       upk2(Tq23, Tqs[2], Tqs[3]);
        upk2(ovp.x, oos[0], oos[1]);      upk2(ovp.y, oos[2], oos[3]);

        float ra = 1.f;
        if (dgi == 0) ra -= w0 + w1; else if (dgi == 1) ra -= w0;
        if (dgi == HH-1) ra -= w0 + w1; else if (dgi == HH-2) ra -= w0;
#pragma unroll
        for (int k = 0; k < 4; k++) {
            int gj = dgj0 + k;
            float rb = 1.f;
            if (gj == 0) rb -= w0 + w1; else if (gj == 1) rb -= w0;
            if (gj == WW-1) rb -= w0 + w1; else if (gj == WW-2) rb -= w0;
            float p = ra*rb - 2.f*convs[k];
            float arg = oos[k] - p - Tqs[k];
            float un  = sigmoid_fast(arg);
            uo[k] = un; ao[k] = arg;
            float yc = (float)(gj+1) - CC;
            s0 += un; sy += un*yc; syy += un*yc*yc;
        }
    }

    *(float4*)(u_out + dgidx) = make_float4(uo[0],uo[1],uo[2],uo[3]);
    if (wout)
        *(float4*)(out + (size_t)b*NPIX + dgidx) = make_float4(ao[0],ao[1],ao[2],ao[3]);

    moments3_reduce(s0, sy, syy, i0, g_sums[(t+1)%3][b], rowred, tid);
}

__global__ __launch_bounds__(256, 5) void step_kernel(const float* __restrict__ o,
                                                      float* __restrict__ out, int t)
{
    __shared__ __align__(16) float u_s[36][40];
    __shared__ __align__(16) float q_s[33][40];
    __shared__ __align__(16) float t_s[36][36];
    __shared__ __align__(16) float txq_s[33][36];
    __shared__ __align__(16) float tyq_s[33][36];
    __shared__ float sc[5];
    __shared__ float rowred[32][3];

    int tid = threadIdx.x;
    int b  = blockIdx.z;
    int i0 = blockIdx.y * 32, j0 = blockIdx.x * 32;

    const float* u_in  = g_u[t & 1]     + (size_t)b * NPIX;
    const float* q_in  = g_q[t & 1]     + (size_t)b * NPIX;
    float*       u_out = g_u[(t+1) & 1] + (size_t)b * NPIX;
    float*       q_out = g_q[(t+1) & 1] + (size_t)b * NPIX;
    const float* ob    = o              + (size_t)b * NPIX;

    // Block-uniform branch: tile needs no border handling anywhere.
    bool interior = (blockIdx.x > 0) & (blockIdx.x < 15) &
                    (blockIdx.y > 0) & (blockIdx.y < 15);
    if (interior)
        step_impl<true >(ob, u_in, q_in, u_out, q_out, out, b, i0, j0, tid, t,
                         u_s, q_s, t_s, txq_s, tyq_s, sc, rowred);
    else
        step_impl<false>(ob, u_in, q_in, u_out, q_out, out, b, i0, j0, tid, t,
                         u_s, q_s, t_s, txq_s, tyq_s, sc, rowred);
}

extern "C" void kernel_launch(void* const* d_in, const int* in_sizes, int n_in,
                              void* d_out, int out_size) {
    const float* o = (const float*)d_in[0];
    float* out = (float*)d_out;
    (void)in_sizes; (void)n_in; (void)out_size;

    dim3 grid(WW/32, HH/32, BB);

    zero_sums_kernel<<<1, 256>>>();

    // PDL: overlap each kernel's launch machinery + o-prefetch with the
    // previous kernel's tail; griddepcontrol.wait in-kernel preserves ordering.
    cudaLaunchAttribute attr[1];
    attr[0].id = cudaLaunchAttributeProgrammaticStreamSerialization;
    attr[0].val.programmaticStreamSerializationAllowed = 1;

    {
        cudaLaunchConfig_t cfg = {};
        cfg.gridDim = grid; cfg.blockDim = dim3(256,1,1);
        cfg.stream = 0; cfg.attrs = attr; cfg.numAttrs = 1;
        cudaLaunchKernelEx(&cfg, init_kernel, o);
    }
    for (int t = 0; t < ITERS; t++) {
        cudaLaunchConfig_t cfg = {};
        cfg.gridDim = grid; cfg.blockDim = dim3(256,1,1);
        cfg.stream = 0; cfg.attrs = attr; cfg.numAttrs = 1;
        float* op = (t == ITERS-1) ? out : nullptr;
        cudaLaunchKernelEx(&cfg, step_kernel, o, op, t);
    }
}